// round 5
// baseline (speedup 1.0000x reference)
#include <cuda_runtime.h>
#include <math.h>
#include <cstdint>
#include <cstddef>

// ---------------- problem constants ----------------
#define T_TOK   2048
#define DIMX    2048
#define QKVC    3072      // (32 + 2*8) * 64
#define NKV     8
#define WIN     128
#define TQ      16
#define KROWS   143

// Scratch (no allocs allowed)
__device__ float g_qkv[(size_t)T_TOK * QKVC];
__device__ float g_attn[(size_t)T_TOK * DIMX];
__device__ float g_xc[(size_t)T_TOK * DIMX];      // tf32-rounded x
__device__ float g_wqkvc[(size_t)QKVC * DIMX];    // tf32-rounded Wqkv
__device__ float g_woc[(size_t)DIMX * DIMX];      // tf32-rounded Wo

// ---------------- helpers ----------------
__device__ __forceinline__ uint32_t smem_u32(const void* p) {
    uint32_t a;
    asm("{ .reg .u64 t; cvta.to.shared.u64 t, %1; cvt.u32.u64 %0, t; }"
        : "=r"(a) : "l"(p));
    return a;
}
__device__ __forceinline__ float f2tf32f(float f) {
    uint32_t r;
    asm("cvt.rna.tf32.f32 %0, %1;" : "=r"(r) : "f"(f));
    return __uint_as_float(r);
}
__device__ __forceinline__ void mma_tf32(float* d, const uint32_t* a,
                                         const uint32_t* b) {
    asm volatile(
        "mma.sync.aligned.m16n8k8.row.col.f32.tf32.tf32.f32 "
        "{%0,%1,%2,%3}, {%4,%5,%6,%7}, {%8,%9}, {%0,%1,%2,%3};"
        : "+f"(d[0]), "+f"(d[1]), "+f"(d[2]), "+f"(d[3])
        : "r"(a[0]), "r"(a[1]), "r"(a[2]), "r"(a[3]), "r"(b[0]), "r"(b[1]));
}

// ---------------- tf32 pre-round pass ----------------
__global__ void cvt_tf32_kernel(const float* __restrict__ in,
                                float* __restrict__ out, int n4)
{
    int i = blockIdx.x * blockDim.x + threadIdx.x;
    if (i < n4) {
        float4 v = *(const float4*)(in + (size_t)i * 4);
        v.x = f2tf32f(v.x); v.y = f2tf32f(v.y);
        v.z = f2tf32f(v.z); v.w = f2tf32f(v.w);
        *(float4*)(out + (size_t)i * 4) = v;
    }
}

// ---------------- tf32 mma.sync GEMM (vectorized frags, no in-loop cvt) ----
// C[M, Ntot] = A[M, K] * B[Ntot, K]^T + bias.  Inputs MUST be tf32-pre-rounded.
// k-slot permutation: MMA instance j uses physical k = 4*s + j (s = slot 0..7),
// so each thread's frags for all 4 j are two float4 loads per row/col.
#define GBM 128
#define GBN 128
#define GBK 32
#define PADW 48                    // floats per smem row; 12%8==4 -> LDS.128 conflict-free
#define SSTG (GBM * PADW * 2)      // floats per stage (A + B) = 12288
#define GS   4
#define GEMM_SMEM (GS * SSTG * 4)  // 196608 bytes

template <bool DO_ROPE>
__global__ __launch_bounds__(256, 1)
void gemm_mma_tf32(const float* __restrict__ A, const float* __restrict__ B,
                   const float* __restrict__ bias, float* __restrict__ C,
                   int Ntot, int K,
                   const float* __restrict__ cosT, const float* __restrict__ sinT)
{
    extern __shared__ float smf[];
    const uint32_t sbase = smem_u32(smf);

    const int tid  = threadIdx.x;
    const int lane = tid & 31;
    const int wid  = tid >> 5;
    const int warpM = wid & 3;       // 4 warps along M (32 rows each)
    const int warpN = wid >> 2;      // 2 warps along N (64 cols each)
    const int gid = lane >> 2;       // 0..7
    const int tig = lane & 3;        // 0..3

    const int m0 = blockIdx.y * GBM;
    const int n0 = blockIdx.x * GBN;
    const int niter = K / GBK;

    const float* Ag = A + (size_t)m0 * K;
    const float* Bg = B + (size_t)n0 * K;

    const int r0 = tid >> 3;         // 0..31
    const int c4 = (tid & 7) * 4;    // 0..28

    float acc[2][8][4];
#pragma unroll
    for (int mt = 0; mt < 2; mt++)
#pragma unroll
        for (int nt = 0; nt < 8; nt++)
#pragma unroll
            for (int z = 0; z < 4; z++) acc[mt][nt][z] = 0.f;

    auto issue = [&](int kt, int s) {
        if (kt < niter) {
            uint32_t abase = sbase + (uint32_t)(s * SSTG + r0 * PADW + c4) * 4;
            const float* ap = Ag + (size_t)r0 * K + kt * GBK + c4;
            const float* bp = Bg + (size_t)r0 * K + kt * GBK + c4;
            uint32_t bbase = abase + GBM * PADW * 4;
#pragma unroll
            for (int i = 0; i < 4; i++) {
                asm volatile("cp.async.cg.shared.global [%0], [%1], 16;"
                             :: "r"(abase + i * 32 * PADW * 4),
                                "l"(ap + (size_t)i * 32 * K) : "memory");
                asm volatile("cp.async.cg.shared.global [%0], [%1], 16;"
                             :: "r"(bbase + i * 32 * PADW * 4),
                                "l"(bp + (size_t)i * 32 * K) : "memory");
            }
        }
        asm volatile("cp.async.commit_group;" ::: "memory");
    };

    issue(0, 0);
    issue(1, 1);
    issue(2, 2);

    for (int it = 0; it < niter; it++) {
        asm volatile("cp.async.wait_group 2;" ::: "memory");
        __syncthreads();

        const int s = it & (GS - 1);
        const float* As = smf + s * SSTG;
        const float* Bs = As + GBM * PADW;

        // fragment loads: float4 pairs (phys k = 4*tig + j and 4*tig + 16 + j)
        float4 a4[2][2][2];   // [mt][row/row+8][lo/hi slot half]
#pragma unroll
        for (int mt = 0; mt < 2; mt++) {
            int row = warpM * 32 + mt * 16 + gid;
            a4[mt][0][0] = *(const float4*)&As[row * PADW + 4 * tig];
            a4[mt][0][1] = *(const float4*)&As[row * PADW + 4 * tig + 16];
            a4[mt][1][0] = *(const float4*)&As[(row + 8) * PADW + 4 * tig];
            a4[mt][1][1] = *(const float4*)&As[(row + 8) * PADW + 4 * tig + 16];
        }
        float4 b4[8][2];
#pragma unroll
        for (int nt = 0; nt < 8; nt++) {
            int col = warpN * 64 + nt * 8 + gid;
            b4[nt][0] = *(const float4*)&Bs[col * PADW + 4 * tig];
            b4[nt][1] = *(const float4*)&Bs[col * PADW + 4 * tig + 16];
        }

#pragma unroll
        for (int j = 0; j < 4; j++) {
#pragma unroll
            for (int mt = 0; mt < 2; mt++) {
                uint32_t afr[4];
                afr[0] = __float_as_uint(((const float*)&a4[mt][0][0])[j]);
                afr[1] = __float_as_uint(((const float*)&a4[mt][1][0])[j]);
                afr[2] = __float_as_uint(((const float*)&a4[mt][0][1])[j]);
                afr[3] = __float_as_uint(((const float*)&a4[mt][1][1])[j]);
#pragma unroll
                for (int nt = 0; nt < 8; nt++) {
                    uint32_t bfr[2];
                    bfr[0] = __float_as_uint(((const float*)&b4[nt][0])[j]);
                    bfr[1] = __float_as_uint(((const float*)&b4[nt][1])[j]);
                    mma_tf32(acc[mt][nt], afr, bfr);
                }
            }
        }
        __syncthreads();
        issue(it + 3, (it + 3) & (GS - 1));
    }

    // ---- epilogue (bias, optional fused RoPE for cols < 2560) ----
    const bool rope_tile = DO_ROPE && (n0 < 2560);
#pragma unroll
    for (int mt = 0; mt < 2; mt++) {
        int row = m0 + warpM * 32 + mt * 16 + gid;   // token for z0,z1; row+8 for z2,z3
#pragma unroll
        for (int np = 0; np < 4; np++) {
            int colL = n0 + warpN * 64 + np * 8 + 2 * tig;
            int colH = colL + 32;
            float L[4], H[4];
#pragma unroll
            for (int z = 0; z < 4; z++) {
                L[z] = acc[mt][np][z]     + __ldg(&bias[colL + (z & 1)]);
                H[z] = acc[mt][np + 4][z] + __ldg(&bias[colH + (z & 1)]);
            }
            if (rope_tile) {
                int dl = colL & 63;                       // 0..30
                const float* c1 = cosT + (size_t)row * 64;
                const float* s1 = sinT + (size_t)row * 64;
                const float* c2 = c1 + 8 * 64;
                const float* s2 = s1 + 8 * 64;
#pragma unroll
                for (int z = 0; z < 4; z++) {
                    const float* cc = (z < 2) ? c1 : c2;
                    const float* ss = (z < 2) ? s1 : s2;
                    int d = dl + (z & 1);
                    float lo = L[z], hi = H[z];
                    L[z] = lo * cc[d]      - hi * ss[d];
                    H[z] = hi * cc[d + 32] + lo * ss[d + 32];
                }
            }
            *(float2*)(C + (size_t)row * Ntot + colL)       = make_float2(L[0], L[1]);
            *(float2*)(C + (size_t)(row + 8) * Ntot + colL) = make_float2(L[2], L[3]);
            *(float2*)(C + (size_t)row * Ntot + colH)       = make_float2(H[0], H[1]);
            *(float2*)(C + (size_t)(row + 8) * Ntot + colH) = make_float2(H[2], H[3]);
        }
    }
}

// ---------------- SWA (stores tf32-rounded outputs for GEMM2) ----------------
#define ATTN_SMEM_FLOATS (64*144 + 144*64 + 64*64 + 64*129 + 64)

__global__ __launch_bounds__(256, 1)
void swa_kernel(const float* __restrict__ sinks)
{
    extern __shared__ float sm[];
    float* Kt  = sm;
    float* V   = Kt + 64 * 144;
    float* Qt  = V  + 144 * 64;
    float* S   = Qt + 64 * 64;
    float* den = S  + 64 * 129;

    const int tid = threadIdx.x;
    const int t0  = blockIdx.x * TQ;
    const int kvh = blockIdx.y;

    for (int idx = tid; idx < KROWS * 64; idx += 256) {
        int u = idx >> 6, d = idx & 63;
        int j = t0 - 127 + u;
        float kv = 0.f, vv = 0.f;
        if (j >= 0) {
            const float* r = g_qkv + (size_t)j * QKVC;
            kv = r[2048 + kvh * 64 + d];
            vv = r[2560 + kvh * 64 + d];
        }
        Kt[d * 144 + u] = kv;
        V[u * 64 + d]   = vv;
    }
    for (int idx = tid; idx < 64 * 64; idx += 256) {
        int r = idx >> 6, d = idx & 63;
        int i = r >> 2, g = r & 3;
        Qt[d * 64 + r] =
            g_qkv[(size_t)(t0 + i) * QKVC + (kvh * 4 + g) * 64 + d] * 0.125f;
    }
    __syncthreads();

    {
        const int c = tid & 31;
#pragma unroll
        for (int half = 0; half < 2; half++) {
            const int a = (tid >> 5) + half * 8;
            float acc[16];
#pragma unroll
            for (int z = 0; z < 16; z++) acc[z] = 0.f;
#pragma unroll 8
            for (int d = 0; d < 64; d++) {
                float q0 = Qt[d * 64 + 4 * a + 0];
                float q1 = Qt[d * 64 + 4 * a + 1];
                float q2 = Qt[d * 64 + 4 * a + 2];
                float q3 = Qt[d * 64 + 4 * a + 3];
                float k0 = Kt[d * 144 + a + c];
                float k1 = Kt[d * 144 + a + c + 32];
                float k2 = Kt[d * 144 + a + c + 64];
                float k3 = Kt[d * 144 + a + c + 96];
                acc[0]  += q0 * k0; acc[1]  += q0 * k1; acc[2]  += q0 * k2; acc[3]  += q0 * k3;
                acc[4]  += q1 * k0; acc[5]  += q1 * k1; acc[6]  += q1 * k2; acc[7]  += q1 * k3;
                acc[8]  += q2 * k0; acc[9]  += q2 * k1; acc[10] += q2 * k2; acc[11] += q2 * k3;
                acc[12] += q3 * k0; acc[13] += q3 * k1; acc[14] += q3 * k2; acc[15] += q3 * k3;
            }
#pragma unroll
            for (int g = 0; g < 4; g++)
#pragma unroll
                for (int kk = 0; kk < 4; kk++)
                    S[(4 * a + g) * 129 + c + kk * 32] = acc[g * 4 + kk];
        }
    }
    __syncthreads();

    {
        const int warp = tid >> 5, lane = tid & 31;
        for (int rr = 0; rr < 8; rr++) {
            int r = warp * 8 + rr;
            int i = r >> 2, g = r & 3;
            int t = t0 + i;
            int wmin = 127 - t;
            float s[4];
#pragma unroll
            for (int kk = 0; kk < 4; kk++) {
                int w = lane + kk * 32;
                float v = S[r * 129 + w];
                s[kk] = (w < wmin) ? -1e30f : v;
            }
            float m = fmaxf(fmaxf(s[0], s[1]), fmaxf(s[2], s[3]));
#pragma unroll
            for (int o = 16; o; o >>= 1)
                m = fmaxf(m, __shfl_xor_sync(0xffffffffu, m, o));
            float snk = __ldg(&sinks[kvh * 4 + g]);
            m = fmaxf(m, snk);
            float sum = 0.f;
#pragma unroll
            for (int kk = 0; kk < 4; kk++) {
                float e = __expf(s[kk] - m);
                S[r * 129 + lane + kk * 32] = e;
                sum += e;
            }
#pragma unroll
            for (int o = 16; o; o >>= 1)
                sum += __shfl_xor_sync(0xffffffffu, sum, o);
            sum += __expf(snk - m);
            if (lane == 0) den[r] = 1.0f / sum;
        }
    }
    __syncthreads();

    {
        const int b = tid >> 4;
        const int e = tid & 15;
        float o_[4][4];
#pragma unroll
        for (int g = 0; g < 4; g++)
#pragma unroll
            for (int z = 0; z < 4; z++) o_[g][z] = 0.f;

        for (int w = 0; w < 128; w++) {
            float4 v4 = *(const float4*)(V + (b + w) * 64 + e * 4);
#pragma unroll
            for (int g = 0; g < 4; g++) {
                float p = S[(4 * b + g) * 129 + w];
                o_[g][0] += p * v4.x;
                o_[g][1] += p * v4.y;
                o_[g][2] += p * v4.z;
                o_[g][3] += p * v4.w;
            }
        }
        const int t = t0 + b;
#pragma unroll
        for (int g = 0; g < 4; g++) {
            float inv = den[4 * b + g];
            float4 r;
            r.x = f2tf32f(o_[g][0] * inv);
            r.y = f2tf32f(o_[g][1] * inv);
            r.z = f2tf32f(o_[g][2] * inv);
            r.w = f2tf32f(o_[g][3] * inv);
            *(float4*)(g_attn + (size_t)t * DIMX + (kvh * 4 + g) * 64 + e * 4) = r;
        }
    }
}

// ---------------- host ----------------
extern "C" void kernel_launch(void* const* d_in, const int* in_sizes, int n_in,
                              void* d_out, int out_size)
{
    (void)in_sizes; (void)n_in; (void)out_size;
    const float* x     = (const float*)d_in[0];
    const float* cosT  = (const float*)d_in[1];
    const float* sinT  = (const float*)d_in[2];
    const float* Wqkv  = (const float*)d_in[3];
    const float* bqkv  = (const float*)d_in[4];
    const float* Wo    = (const float*)d_in[5];
    const float* bo    = (const float*)d_in[6];
    const float* sinks = (const float*)d_in[7];
    float* out = (float*)d_out;

    float *qkv = nullptr, *att = nullptr;
    float *xc = nullptr, *wqkvc = nullptr, *woc = nullptr;
    cudaGetSymbolAddress((void**)&qkv,   g_qkv);
    cudaGetSymbolAddress((void**)&att,   g_attn);
    cudaGetSymbolAddress((void**)&xc,    g_xc);
    cudaGetSymbolAddress((void**)&wqkvc, g_wqkvc);
    cudaGetSymbolAddress((void**)&woc,   g_woc);

    cudaFuncSetAttribute(gemm_mma_tf32<true>,
                         cudaFuncAttributeMaxDynamicSharedMemorySize, GEMM_SMEM);
    cudaFuncSetAttribute(gemm_mma_tf32<false>,
                         cudaFuncAttributeMaxDynamicSharedMemorySize, GEMM_SMEM);
    const int attn_smem = ATTN_SMEM_FLOATS * 4;
    cudaFuncSetAttribute(swa_kernel,
                         cudaFuncAttributeMaxDynamicSharedMemorySize, attn_smem);

    // 0) tf32 pre-rounding passes
    cvt_tf32_kernel<<<(T_TOK * DIMX / 4 + 255) / 256, 256>>>(x,    xc,    T_TOK * DIMX / 4);
    cvt_tf32_kernel<<<(QKVC * DIMX / 4 + 255) / 256, 256>>>(Wqkv, wqkvc, QKVC * DIMX / 4);
    cvt_tf32_kernel<<<(DIMX * DIMX / 4 + 255) / 256, 256>>>(Wo,   woc,   DIMX * DIMX / 4);

    // 1) qkv = x @ Wqkv^T + bqkv, RoPE fused into epilogue
    gemm_mma_tf32<true><<<dim3(QKVC / GBN, T_TOK / GBM), 256, GEMM_SMEM>>>(
        xc, wqkvc, bqkv, qkv, QKVC, DIMX, cosT, sinT);
    // 2) sliding-window attention with sink (emits tf32-rounded attn)
    swa_kernel<<<dim3(T_TOK / TQ, NKV), 256, attn_smem>>>(sinks);
    // 3) out = attn @ Wo^T + bo
    gemm_mma_tf32<false><<<dim3(DIMX / GBN, T_TOK / GBM), 256, GEMM_SMEM>>>(
        att, woc, bo, out, DIMX, DIMX, nullptr, nullptr);
}

// round 6
// speedup vs baseline: 1.0877x; 1.0877x over previous
#include <cuda_runtime.h>
#include <math.h>
#include <cstdint>
#include <cstddef>

// ---------------- problem constants ----------------
#define T_TOK   2048
#define DIMX    2048
#define QKVC    3072      // (32 + 2*8) * 64
#define NKV     8
#define WIN     128
#define TQ      16
#define KROWS   143

// Scratch (no allocs allowed)
__device__ float g_qkv[(size_t)T_TOK * QKVC];
__device__ float g_attn[(size_t)T_TOK * DIMX];
__device__ float g_xc[(size_t)T_TOK * DIMX];      // tf32-rounded x
__device__ float g_wqkvc[(size_t)QKVC * DIMX];    // tf32-rounded Wqkv
__device__ float g_woc[(size_t)DIMX * DIMX];      // tf32-rounded Wo

// ---------------- helpers ----------------
__device__ __forceinline__ uint32_t smem_u32(const void* p) {
    uint32_t a;
    asm("{ .reg .u64 t; cvta.to.shared.u64 t, %1; cvt.u32.u64 %0, t; }"
        : "=r"(a) : "l"(p));
    return a;
}
__device__ __forceinline__ float f2tf32f(float f) {
    uint32_t r;
    asm("cvt.rna.tf32.f32 %0, %1;" : "=r"(r) : "f"(f));
    return __uint_as_float(r);
}
__device__ __forceinline__ void mma_tf32(float* d, const uint32_t* a,
                                         const uint32_t* b) {
    asm volatile(
        "mma.sync.aligned.m16n8k8.row.col.f32.tf32.tf32.f32 "
        "{%0,%1,%2,%3}, {%4,%5,%6,%7}, {%8,%9}, {%0,%1,%2,%3};"
        : "+f"(d[0]), "+f"(d[1]), "+f"(d[2]), "+f"(d[3])
        : "r"(a[0]), "r"(a[1]), "r"(a[2]), "r"(a[3]), "r"(b[0]), "r"(b[1]));
}

// ---------------- tf32 pre-round pass ----------------
__global__ void cvt_tf32_kernel(const float* __restrict__ in,
                                float* __restrict__ out, int n4)
{
    int i = blockIdx.x * blockDim.x + threadIdx.x;
    if (i < n4) {
        float4 v = *(const float4*)(in + (size_t)i * 4);
        v.x = f2tf32f(v.x); v.y = f2tf32f(v.y);
        v.z = f2tf32f(v.z); v.w = f2tf32f(v.w);
        *(float4*)(out + (size_t)i * 4) = v;
    }
}

// ---------------- tf32 mma.sync GEMM (R4 skeleton, pre-rounded inputs) ------
// C[M, Ntot] = A[M, K] * B[Ntot, K]^T + bias.  Inputs MUST be tf32-pre-rounded.
// CTA tile 128x128x32, 3-stage cp.async pipeline, 256 threads, 2 CTAs/SM.
#define GBM 128
#define GBN 128
#define GBK 32
#define PADW 36                    // floats per smem row (conflict-free frags)
#define SSTG (GBM * PADW * 2)      // floats per stage (A + B) = 9216
#define GEMM_SMEM (3 * SSTG * 4)   // 110592 bytes

template <bool DO_ROPE>
__global__ __launch_bounds__(256, 1)
void gemm_mma_tf32(const float* __restrict__ A, const float* __restrict__ B,
                   const float* __restrict__ bias, float* __restrict__ C,
                   int Ntot, int K,
                   const float* __restrict__ cosT, const float* __restrict__ sinT)
{
    extern __shared__ float smf[];
    const uint32_t sbase = smem_u32(smf);

    const int tid  = threadIdx.x;
    const int lane = tid & 31;
    const int wid  = tid >> 5;
    const int warpM = wid & 3;       // 4 warps along M (32 rows each)
    const int warpN = wid >> 2;      // 2 warps along N (64 cols each)
    const int gid = lane >> 2;       // 0..7
    const int tig = lane & 3;        // 0..3

    const int m0 = blockIdx.y * GBM;
    const int n0 = blockIdx.x * GBN;
    const int niter = K / GBK;       // 64

    const float* Ag = A + (size_t)m0 * K;
    const float* Bg = B + (size_t)n0 * K;

    const int r0 = tid >> 3;         // 0..31
    const int c4 = (tid & 7) * 4;    // 0..28

    float acc[2][8][4];
#pragma unroll
    for (int mt = 0; mt < 2; mt++)
#pragma unroll
        for (int nt = 0; nt < 8; nt++)
#pragma unroll
            for (int z = 0; z < 4; z++) acc[mt][nt][z] = 0.f;

    auto issue = [&](int kt, int s) {
        if (kt < niter) {
            uint32_t abase = sbase + (uint32_t)(s * SSTG + r0 * PADW + c4) * 4;
            const float* ap = Ag + (size_t)r0 * K + kt * GBK + c4;
            const float* bp = Bg + (size_t)r0 * K + kt * GBK + c4;
            uint32_t bbase = abase + GBM * PADW * 4;
#pragma unroll
            for (int i = 0; i < 4; i++) {
                asm volatile("cp.async.cg.shared.global [%0], [%1], 16;"
                             :: "r"(abase + i * 32 * PADW * 4),
                                "l"(ap + (size_t)i * 32 * K) : "memory");
                asm volatile("cp.async.cg.shared.global [%0], [%1], 16;"
                             :: "r"(bbase + i * 32 * PADW * 4),
                                "l"(bp + (size_t)i * 32 * K) : "memory");
            }
        }
        asm volatile("cp.async.commit_group;" ::: "memory");
    };

    issue(0, 0);
    issue(1, 1);

    const uint32_t* Asu;
    const uint32_t* Bsu;

    for (int it = 0; it < niter; it++) {
        asm volatile("cp.async.wait_group 1;" ::: "memory");
        __syncthreads();

        const int s = it % 3;
        Asu = (const uint32_t*)(smf + s * SSTG);
        Bsu = Asu + GBM * PADW;

#pragma unroll
        for (int ks = 0; ks < 4; ks++) {
            const int k = ks * 8;
            uint32_t afr[2][4];
#pragma unroll
            for (int mt = 0; mt < 2; mt++) {
                int row = warpM * 32 + mt * 16 + gid;
                afr[mt][0] = Asu[row * PADW + k + tig];
                afr[mt][1] = Asu[(row + 8) * PADW + k + tig];
                afr[mt][2] = Asu[row * PADW + k + tig + 4];
                afr[mt][3] = Asu[(row + 8) * PADW + k + tig + 4];
            }
            uint32_t bfr[8][2];
#pragma unroll
            for (int nt = 0; nt < 8; nt++) {
                int col = warpN * 64 + nt * 8 + gid;
                bfr[nt][0] = Bsu[col * PADW + k + tig];
                bfr[nt][1] = Bsu[col * PADW + k + tig + 4];
            }
#pragma unroll
            for (int mt = 0; mt < 2; mt++)
#pragma unroll
                for (int nt = 0; nt < 8; nt++)
                    mma_tf32(acc[mt][nt], afr[mt], bfr[nt]);
        }
        __syncthreads();
        issue(it + 2, (it + 2) % 3);
    }

    // ---- epilogue: bias + optional fused RoPE (cols < 2560 are q/k heads) --
    const bool rope_tile = DO_ROPE && (n0 < 2560);
#pragma unroll
    for (int mt = 0; mt < 2; mt++) {
        int row = m0 + warpM * 32 + mt * 16 + gid;   // token for z0,z1; row+8 for z2,z3
#pragma unroll
        for (int np = 0; np < 4; np++) {
            int colL = n0 + warpN * 64 + np * 8 + 2 * tig;   // colL % 64 in [0,31)
            int colH = colL + 32;
            float L[4], H[4];
#pragma unroll
            for (int z = 0; z < 4; z++) {
                L[z] = acc[mt][np][z]     + __ldg(&bias[colL + (z & 1)]);
                H[z] = acc[mt][np + 4][z] + __ldg(&bias[colH + (z & 1)]);
            }
            if (rope_tile) {
                int dl = colL & 63;                       // 0..30
                const float* c1 = cosT + (size_t)row * 64;
                const float* s1 = sinT + (size_t)row * 64;
                const float* c2 = c1 + 8 * 64;
                const float* s2 = s1 + 8 * 64;
#pragma unroll
                for (int z = 0; z < 4; z++) {
                    const float* cc = (z < 2) ? c1 : c2;
                    const float* ss = (z < 2) ? s1 : s2;
                    int d = dl + (z & 1);
                    float lo = L[z], hi = H[z];
                    L[z] = lo * cc[d]      - hi * ss[d];
                    H[z] = hi * cc[d + 32] + lo * ss[d + 32];
                }
            }
            *(float2*)(C + (size_t)row * Ntot + colL)       = make_float2(L[0], L[1]);
            *(float2*)(C + (size_t)(row + 8) * Ntot + colL) = make_float2(L[2], L[3]);
            *(float2*)(C + (size_t)row * Ntot + colH)       = make_float2(H[0], H[1]);
            *(float2*)(C + (size_t)(row + 8) * Ntot + colH) = make_float2(H[2], H[3]);
        }
    }
}

// ---------------- SWA (emits tf32-rounded attn for GEMM2) ----------------
#define ATTN_SMEM_FLOATS (64*144 + 144*64 + 64*64 + 64*129 + 64)

__global__ __launch_bounds__(256, 1)
void swa_kernel(const float* __restrict__ sinks)
{
    extern __shared__ float sm[];
    float* Kt  = sm;
    float* V   = Kt + 64 * 144;
    float* Qt  = V  + 144 * 64;
    float* S   = Qt + 64 * 64;
    float* den = S  + 64 * 129;

    const int tid = threadIdx.x;
    const int t0  = blockIdx.x * TQ;
    const int kvh = blockIdx.y;

    for (int idx = tid; idx < KROWS * 64; idx += 256) {
        int u = idx >> 6, d = idx & 63;
        int j = t0 - 127 + u;
        float kv = 0.f, vv = 0.f;
        if (j >= 0) {
            const float* r = g_qkv + (size_t)j * QKVC;
            kv = r[2048 + kvh * 64 + d];
            vv = r[2560 + kvh * 64 + d];
        }
        Kt[d * 144 + u] = kv;
        V[u * 64 + d]   = vv;
    }
    for (int idx = tid; idx < 64 * 64; idx += 256) {
        int r = idx >> 6, d = idx & 63;
        int i = r >> 2, g = r & 3;
        Qt[d * 64 + r] =
            g_qkv[(size_t)(t0 + i) * QKVC + (kvh * 4 + g) * 64 + d] * 0.125f;
    }
    __syncthreads();

    {
        const int c = tid & 31;
#pragma unroll
        for (int half = 0; half < 2; half++) {
            const int a = (tid >> 5) + half * 8;
            float acc[16];
#pragma unroll
            for (int z = 0; z < 16; z++) acc[z] = 0.f;
#pragma unroll 8
            for (int d = 0; d < 64; d++) {
                float q0 = Qt[d * 64 + 4 * a + 0];
                float q1 = Qt[d * 64 + 4 * a + 1];
                float q2 = Qt[d * 64 + 4 * a + 2];
                float q3 = Qt[d * 64 + 4 * a + 3];
                float k0 = Kt[d * 144 + a + c];
                float k1 = Kt[d * 144 + a + c + 32];
                float k2 = Kt[d * 144 + a + c + 64];
                float k3 = Kt[d * 144 + a + c + 96];
                acc[0]  += q0 * k0; acc[1]  += q0 * k1; acc[2]  += q0 * k2; acc[3]  += q0 * k3;
                acc[4]  += q1 * k0; acc[5]  += q1 * k1; acc[6]  += q1 * k2; acc[7]  += q1 * k3;
                acc[8]  += q2 * k0; acc[9]  += q2 * k1; acc[10] += q2 * k2; acc[11] += q2 * k3;
                acc[12] += q3 * k0; acc[13] += q3 * k1; acc[14] += q3 * k2; acc[15] += q3 * k3;
            }
#pragma unroll
            for (int g = 0; g < 4; g++)
#pragma unroll
                for (int kk = 0; kk < 4; kk++)
                    S[(4 * a + g) * 129 + c + kk * 32] = acc[g * 4 + kk];
        }
    }
    __syncthreads();

    {
        const int warp = tid >> 5, lane = tid & 31;
        for (int rr = 0; rr < 8; rr++) {
            int r = warp * 8 + rr;
            int i = r >> 2, g = r & 3;
            int t = t0 + i;
            int wmin = 127 - t;
            float s[4];
#pragma unroll
            for (int kk = 0; kk < 4; kk++) {
                int w = lane + kk * 32;
                float v = S[r * 129 + w];
                s[kk] = (w < wmin) ? -1e30f : v;
            }
            float m = fmaxf(fmaxf(s[0], s[1]), fmaxf(s[2], s[3]));
#pragma unroll
            for (int o = 16; o; o >>= 1)
                m = fmaxf(m, __shfl_xor_sync(0xffffffffu, m, o));
            float snk = __ldg(&sinks[kvh * 4 + g]);
            m = fmaxf(m, snk);
            float sum = 0.f;
#pragma unroll
            for (int kk = 0; kk < 4; kk++) {
                float e = __expf(s[kk] - m);
                S[r * 129 + lane + kk * 32] = e;
                sum += e;
            }
#pragma unroll
            for (int o = 16; o; o >>= 1)
                sum += __shfl_xor_sync(0xffffffffu, sum, o);
            sum += __expf(snk - m);
            if (lane == 0) den[r] = 1.0f / sum;
        }
    }
    __syncthreads();

    {
        const int b = tid >> 4;
        const int e = tid & 15;
        float o_[4][4];
#pragma unroll
        for (int g = 0; g < 4; g++)
#pragma unroll
            for (int z = 0; z < 4; z++) o_[g][z] = 0.f;

        for (int w = 0; w < 128; w++) {
            float4 v4 = *(const float4*)(V + (b + w) * 64 + e * 4);
#pragma unroll
            for (int g = 0; g < 4; g++) {
                float p = S[(4 * b + g) * 129 + w];
                o_[g][0] += p * v4.x;
                o_[g][1] += p * v4.y;
                o_[g][2] += p * v4.z;
                o_[g][3] += p * v4.w;
            }
        }
        const int t = t0 + b;
#pragma unroll
        for (int g = 0; g < 4; g++) {
            float inv = den[4 * b + g];
            float4 r;
            r.x = f2tf32f(o_[g][0] * inv);
            r.y = f2tf32f(o_[g][1] * inv);
            r.z = f2tf32f(o_[g][2] * inv);
            r.w = f2tf32f(o_[g][3] * inv);
            *(float4*)(g_attn + (size_t)t * DIMX + (kvh * 4 + g) * 64 + e * 4) = r;
        }
    }
}

// ---------------- host ----------------
extern "C" void kernel_launch(void* const* d_in, const int* in_sizes, int n_in,
                              void* d_out, int out_size)
{
    (void)in_sizes; (void)n_in; (void)out_size;
    const float* x     = (const float*)d_in[0];
    const float* cosT  = (const float*)d_in[1];
    const float* sinT  = (const float*)d_in[2];
    const float* Wqkv  = (const float*)d_in[3];
    const float* bqkv  = (const float*)d_in[4];
    const float* Wo    = (const float*)d_in[5];
    const float* bo    = (const float*)d_in[6];
    const float* sinks = (const float*)d_in[7];
    float* out = (float*)d_out;

    float *qkv = nullptr, *att = nullptr;
    float *xc = nullptr, *wqkvc = nullptr, *woc = nullptr;
    cudaGetSymbolAddress((void**)&qkv,   g_qkv);
    cudaGetSymbolAddress((void**)&att,   g_attn);
    cudaGetSymbolAddress((void**)&xc,    g_xc);
    cudaGetSymbolAddress((void**)&wqkvc, g_wqkvc);
    cudaGetSymbolAddress((void**)&woc,   g_woc);

    cudaFuncSetAttribute(gemm_mma_tf32<true>,
                         cudaFuncAttributeMaxDynamicSharedMemorySize, GEMM_SMEM);
    cudaFuncSetAttribute(gemm_mma_tf32<false>,
                         cudaFuncAttributeMaxDynamicSharedMemorySize, GEMM_SMEM);
    const int attn_smem = ATTN_SMEM_FLOATS * 4;
    cudaFuncSetAttribute(swa_kernel,
                         cudaFuncAttributeMaxDynamicSharedMemorySize, attn_smem);

    // 0) tf32 pre-rounding passes
    cvt_tf32_kernel<<<(T_TOK * DIMX / 4 + 255) / 256, 256>>>(x,    xc,    T_TOK * DIMX / 4);
    cvt_tf32_kernel<<<(QKVC * DIMX / 4 + 255) / 256, 256>>>(Wqkv, wqkvc, QKVC * DIMX / 4);
    cvt_tf32_kernel<<<(DIMX * DIMX / 4 + 255) / 256, 256>>>(Wo,   woc,   DIMX * DIMX / 4);

    // 1) qkv = x @ Wqkv^T + bqkv, RoPE fused into epilogue
    gemm_mma_tf32<true><<<dim3(QKVC / GBN, T_TOK / GBM), 256, GEMM_SMEM>>>(
        xc, wqkvc, bqkv, qkv, QKVC, DIMX, cosT, sinT);
    // 2) sliding-window attention with sink (emits tf32-rounded attn)
    swa_kernel<<<dim3(T_TOK / TQ, NKV), 256, attn_smem>>>(sinks);
    // 3) out = attn @ Wo^T + bo
    gemm_mma_tf32<false><<<dim3(DIMX / GBN, T_TOK / GBM), 256, GEMM_SMEM>>>(
        att, woc, bo, out, DIMX, DIMX, nullptr, nullptr);
}

// round 7
// speedup vs baseline: 1.1672x; 1.0731x over previous
#include <cuda_runtime.h>
#include <math.h>
#include <cstdint>
#include <cstddef>

// ---------------- problem constants ----------------
#define T_TOK   2048
#define DIMX    2048
#define QKVC    3072      // (32 + 2*8) * 64
#define NKV     8
#define WIN     128
#define TQ      16
#define KROWS   143

// Scratch (no allocs allowed)
__device__ float g_qkv[(size_t)T_TOK * QKVC];
__device__ float g_attn[(size_t)T_TOK * DIMX];
__device__ float g_xc[(size_t)T_TOK * DIMX];      // tf32-rounded x
__device__ float g_wqkvc[(size_t)QKVC * DIMX];    // tf32-rounded Wqkv
__device__ float g_woc[(size_t)DIMX * DIMX];      // tf32-rounded Wo

// ---------------- helpers ----------------
__device__ __forceinline__ uint32_t smem_u32(const void* p) {
    uint32_t a;
    asm("{ .reg .u64 t; cvta.to.shared.u64 t, %1; cvt.u32.u64 %0, t; }"
        : "=r"(a) : "l"(p));
    return a;
}
__device__ __forceinline__ float f2tf32f(float f) {
    uint32_t r;
    asm("cvt.rna.tf32.f32 %0, %1;" : "=r"(r) : "f"(f));
    return __uint_as_float(r);
}
__device__ __forceinline__ void mma_tf32(float* d, const uint32_t* a,
                                         const uint32_t* b) {
    asm volatile(
        "mma.sync.aligned.m16n8k8.row.col.f32.tf32.tf32.f32 "
        "{%0,%1,%2,%3}, {%4,%5,%6,%7}, {%8,%9}, {%0,%1,%2,%3};"
        : "+f"(d[0]), "+f"(d[1]), "+f"(d[2]), "+f"(d[3])
        : "r"(a[0]), "r"(a[1]), "r"(a[2]), "r"(a[3]), "r"(b[0]), "r"(b[1]));
}

// ---------------- tf32 pre-round pass ----------------
__global__ void cvt_tf32_kernel(const float* __restrict__ in,
                                float* __restrict__ out, int n4)
{
    int i = blockIdx.x * blockDim.x + threadIdx.x;
    if (i < n4) {
        float4 v = *(const float4*)(in + (size_t)i * 4);
        v.x = f2tf32f(v.x); v.y = f2tf32f(v.y);
        v.z = f2tf32f(v.z); v.w = f2tf32f(v.w);
        *(float4*)(out + (size_t)i * 4) = v;
    }
}

// ---------------- tf32 mma.sync GEMM (pre-rounded inputs, 2 CTAs/SM) --------
// C[M, Ntot] = A[M, K] * B[Ntot, K]^T + bias.  Inputs MUST be tf32-pre-rounded.
// CTA tile 128x128x32, 3-stage cp.async pipeline, 256 threads.
#define GBM 128
#define GBN 128
#define GBK 32
#define PADW 36                    // floats per smem row (conflict-free frags)
#define SSTG (GBM * PADW * 2)      // floats per stage (A + B) = 9216
#define GEMM_SMEM (3 * SSTG * 4)   // 110592 bytes

template <bool DO_ROPE>
__global__ __launch_bounds__(256, 2)     // force <=128 regs -> 2 CTAs/SM
void gemm_mma_tf32(const float* __restrict__ A, const float* __restrict__ B,
                   const float* __restrict__ bias, float* __restrict__ C,
                   int Ntot, int K,
                   const float* __restrict__ cosT, const float* __restrict__ sinT)
{
    extern __shared__ float smf[];
    const uint32_t sbase = smem_u32(smf);

    const int tid  = threadIdx.x;
    const int lane = tid & 31;
    const int wid  = tid >> 5;
    const int warpM = wid & 3;       // 4 warps along M (32 rows each)
    const int warpN = wid >> 2;      // 2 warps along N (64 cols each)
    const int gid = lane >> 2;       // 0..7
    const int tig = lane & 3;        // 0..3

    const int m0 = blockIdx.y * GBM;
    const int n0 = blockIdx.x * GBN;
    const int niter = K / GBK;       // 64

    const float* Ag = A + (size_t)m0 * K;
    const float* Bg = B + (size_t)n0 * K;

    const int r0 = tid >> 3;         // 0..31
    const int c4 = (tid & 7) * 4;    // 0..28

    float acc[2][8][4];
#pragma unroll
    for (int mt = 0; mt < 2; mt++)
#pragma unroll
        for (int nt = 0; nt < 8; nt++)
#pragma unroll
            for (int z = 0; z < 4; z++) acc[mt][nt][z] = 0.f;

    auto issue = [&](int kt, int s) {
        if (kt < niter) {
            uint32_t abase = sbase + (uint32_t)(s * SSTG + r0 * PADW + c4) * 4;
            const float* ap = Ag + (size_t)r0 * K + kt * GBK + c4;
            const float* bp = Bg + (size_t)r0 * K + kt * GBK + c4;
            uint32_t bbase = abase + GBM * PADW * 4;
#pragma unroll
            for (int i = 0; i < 4; i++) {
                asm volatile("cp.async.cg.shared.global [%0], [%1], 16;"
                             :: "r"(abase + i * 32 * PADW * 4),
                                "l"(ap + (size_t)i * 32 * K) : "memory");
                asm volatile("cp.async.cg.shared.global [%0], [%1], 16;"
                             :: "r"(bbase + i * 32 * PADW * 4),
                                "l"(bp + (size_t)i * 32 * K) : "memory");
            }
        }
        asm volatile("cp.async.commit_group;" ::: "memory");
    };

    issue(0, 0);
    issue(1, 1);

    for (int it = 0; it < niter; it++) {
        asm volatile("cp.async.wait_group 1;" ::: "memory");
        __syncthreads();

        const int s = it % 3;
        const uint32_t* Asu = (const uint32_t*)(smf + s * SSTG);
        const uint32_t* Bsu = Asu + GBM * PADW;

#pragma unroll
        for (int ks = 0; ks < 4; ks++) {
            const int k = ks * 8;
            uint32_t afr[2][4];
#pragma unroll
            for (int mt = 0; mt < 2; mt++) {
                int row = warpM * 32 + mt * 16 + gid;
                afr[mt][0] = Asu[row * PADW + k + tig];
                afr[mt][1] = Asu[(row + 8) * PADW + k + tig];
                afr[mt][2] = Asu[row * PADW + k + tig + 4];
                afr[mt][3] = Asu[(row + 8) * PADW + k + tig + 4];
            }
            uint32_t bfr[8][2];
#pragma unroll
            for (int nt = 0; nt < 8; nt++) {
                int col = warpN * 64 + nt * 8 + gid;
                bfr[nt][0] = Bsu[col * PADW + k + tig];
                bfr[nt][1] = Bsu[col * PADW + k + tig + 4];
            }
#pragma unroll
            for (int mt = 0; mt < 2; mt++)
#pragma unroll
                for (int nt = 0; nt < 8; nt++)
                    mma_tf32(acc[mt][nt], afr[mt], bfr[nt]);
        }
        __syncthreads();
        issue(it + 2, (it + 2) % 3);
    }

    // ---- epilogue: bias + optional fused RoPE (cols < 2560 are q/k heads) --
    const bool rope_tile = DO_ROPE && (n0 < 2560);
#pragma unroll
    for (int mt = 0; mt < 2; mt++) {
        int row = m0 + warpM * 32 + mt * 16 + gid;   // token for z0,z1; row+8 for z2,z3
#pragma unroll
        for (int np = 0; np < 4; np++) {
            int colL = n0 + warpN * 64 + np * 8 + 2 * tig;   // colL % 64 in [0,31)
            int colH = colL + 32;
            float L[4], H[4];
#pragma unroll
            for (int z = 0; z < 4; z++) {
                L[z] = acc[mt][np][z]     + __ldg(&bias[colL + (z & 1)]);
                H[z] = acc[mt][np + 4][z] + __ldg(&bias[colH + (z & 1)]);
            }
            if (rope_tile) {
                int dl = colL & 63;                       // 0..30
                const float* c1 = cosT + (size_t)row * 64;
                const float* s1 = sinT + (size_t)row * 64;
                const float* c2 = c1 + 8 * 64;
                const float* s2 = s1 + 8 * 64;
#pragma unroll
                for (int z = 0; z < 4; z++) {
                    const float* cc = (z < 2) ? c1 : c2;
                    const float* ss = (z < 2) ? s1 : s2;
                    int d = dl + (z & 1);
                    float lo = L[z], hi = H[z];
                    L[z] = lo * cc[d]      - hi * ss[d];
                    H[z] = hi * cc[d + 32] + lo * ss[d + 32];
                }
            }
            *(float2*)(C + (size_t)row * Ntot + colL)       = make_float2(L[0], L[1]);
            *(float2*)(C + (size_t)(row + 8) * Ntot + colL) = make_float2(L[2], L[3]);
            *(float2*)(C + (size_t)row * Ntot + colH)       = make_float2(H[0], H[1]);
            *(float2*)(C + (size_t)(row + 8) * Ntot + colH) = make_float2(H[2], H[3]);
        }
    }
}

// ---------------- SWA (emits tf32-rounded attn for GEMM2) ----------------
#define ATTN_SMEM_FLOATS (64*144 + 144*64 + 64*64 + 64*129 + 64)

__global__ __launch_bounds__(256, 1)
void swa_kernel(const float* __restrict__ sinks)
{
    extern __shared__ float sm[];
    float* Kt  = sm;
    float* V   = Kt + 64 * 144;
    float* Qt  = V  + 144 * 64;
    float* S   = Qt + 64 * 64;
    float* den = S  + 64 * 129;

    const int tid = threadIdx.x;
    const int t0  = blockIdx.x * TQ;
    const int kvh = blockIdx.y;

    for (int idx = tid; idx < KROWS * 64; idx += 256) {
        int u = idx >> 6, d = idx & 63;
        int j = t0 - 127 + u;
        float kv = 0.f, vv = 0.f;
        if (j >= 0) {
            const float* r = g_qkv + (size_t)j * QKVC;
            kv = r[2048 + kvh * 64 + d];
            vv = r[2560 + kvh * 64 + d];
        }
        Kt[d * 144 + u] = kv;
        V[u * 64 + d]   = vv;
    }
    for (int idx = tid; idx < 64 * 64; idx += 256) {
        int r = idx >> 6, d = idx & 63;
        int i = r >> 2, g = r & 3;
        Qt[d * 64 + r] =
            g_qkv[(size_t)(t0 + i) * QKVC + (kvh * 4 + g) * 64 + d] * 0.125f;
    }
    __syncthreads();

    {
        const int c = tid & 31;
#pragma unroll
        for (int half = 0; half < 2; half++) {
            const int a = (tid >> 5) + half * 8;
            float acc[16];
#pragma unroll
            for (int z = 0; z < 16; z++) acc[z] = 0.f;
#pragma unroll 8
            for (int d = 0; d < 64; d++) {
                float q0 = Qt[d * 64 + 4 * a + 0];
                float q1 = Qt[d * 64 + 4 * a + 1];
                float q2 = Qt[d * 64 + 4 * a + 2];
                float q3 = Qt[d * 64 + 4 * a + 3];
                float k0 = Kt[d * 144 + a + c];
                float k1 = Kt[d * 144 + a + c + 32];
                float k2 = Kt[d * 144 + a + c + 64];
                float k3 = Kt[d * 144 + a + c + 96];
                acc[0]  += q0 * k0; acc[1]  += q0 * k1; acc[2]  += q0 * k2; acc[3]  += q0 * k3;
                acc[4]  += q1 * k0; acc[5]  += q1 * k1; acc[6]  += q1 * k2; acc[7]  += q1 * k3;
                acc[8]  += q2 * k0; acc[9]  += q2 * k1; acc[10] += q2 * k2; acc[11] += q2 * k3;
                acc[12] += q3 * k0; acc[13] += q3 * k1; acc[14] += q3 * k2; acc[15] += q3 * k3;
            }
#pragma unroll
            for (int g = 0; g < 4; g++)
#pragma unroll
                for (int kk = 0; kk < 4; kk++)
                    S[(4 * a + g) * 129 + c + kk * 32] = acc[g * 4 + kk];
        }
    }
    __syncthreads();

    {
        const int warp = tid >> 5, lane = tid & 31;
        for (int rr = 0; rr < 8; rr++) {
            int r = warp * 8 + rr;
            int i = r >> 2, g = r & 3;
            int t = t0 + i;
            int wmin = 127 - t;
            float s[4];
#pragma unroll
            for (int kk = 0; kk < 4; kk++) {
                int w = lane + kk * 32;
                float v = S[r * 129 + w];
                s[kk] = (w < wmin) ? -1e30f : v;
            }
            float m = fmaxf(fmaxf(s[0], s[1]), fmaxf(s[2], s[3]));
#pragma unroll
            for (int o = 16; o; o >>= 1)
                m = fmaxf(m, __shfl_xor_sync(0xffffffffu, m, o));
            float snk = __ldg(&sinks[kvh * 4 + g]);
            m = fmaxf(m, snk);
            float sum = 0.f;
#pragma unroll
            for (int kk = 0; kk < 4; kk++) {
                float e = __expf(s[kk] - m);
                S[r * 129 + lane + kk * 32] = e;
                sum += e;
            }
#pragma unroll
            for (int o = 16; o; o >>= 1)
                sum += __shfl_xor_sync(0xffffffffu, sum, o);
            sum += __expf(snk - m);
            if (lane == 0) den[r] = 1.0f / sum;
        }
    }
    __syncthreads();

    {
        const int b = tid >> 4;
        const int e = tid & 15;
        float o_[4][4];
#pragma unroll
        for (int g = 0; g < 4; g++)
#pragma unroll
            for (int z = 0; z < 4; z++) o_[g][z] = 0.f;

        for (int w = 0; w < 128; w++) {
            float4 v4 = *(const float4*)(V + (b + w) * 64 + e * 4);
#pragma unroll
            for (int g = 0; g < 4; g++) {
                float p = S[(4 * b + g) * 129 + w];
                o_[g][0] += p * v4.x;
                o_[g][1] += p * v4.y;
                o_[g][2] += p * v4.z;
                o_[g][3] += p * v4.w;
            }
        }
        const int t = t0 + b;
#pragma unroll
        for (int g = 0; g < 4; g++) {
            float inv = den[4 * b + g];
            float4 r;
            r.x = f2tf32f(o_[g][0] * inv);
            r.y = f2tf32f(o_[g][1] * inv);
            r.z = f2tf32f(o_[g][2] * inv);
            r.w = f2tf32f(o_[g][3] * inv);
            *(float4*)(g_attn + (size_t)t * DIMX + (kvh * 4 + g) * 64 + e * 4) = r;
        }
    }
}

// ---------------- host ----------------
extern "C" void kernel_launch(void* const* d_in, const int* in_sizes, int n_in,
                              void* d_out, int out_size)
{
    (void)in_sizes; (void)n_in; (void)out_size;
    const float* x     = (const float*)d_in[0];
    const float* cosT  = (const float*)d_in[1];
    const float* sinT  = (const float*)d_in[2];
    const float* Wqkv  = (const float*)d_in[3];
    const float* bqkv  = (const float*)d_in[4];
    const float* Wo    = (const float*)d_in[5];
    const float* bo    = (const float*)d_in[6];
    const float* sinks = (const float*)d_in[7];
    float* out = (float*)d_out;

    float *qkv = nullptr, *att = nullptr;
    float *xc = nullptr, *wqkvc = nullptr, *woc = nullptr;
    cudaGetSymbolAddress((void**)&qkv,   g_qkv);
    cudaGetSymbolAddress((void**)&att,   g_attn);
    cudaGetSymbolAddress((void**)&xc,    g_xc);
    cudaGetSymbolAddress((void**)&wqkvc, g_wqkvc);
    cudaGetSymbolAddress((void**)&woc,   g_woc);

    cudaFuncSetAttribute(gemm_mma_tf32<true>,
                         cudaFuncAttributeMaxDynamicSharedMemorySize, GEMM_SMEM);
    cudaFuncSetAttribute(gemm_mma_tf32<false>,
                         cudaFuncAttributeMaxDynamicSharedMemorySize, GEMM_SMEM);
    const int attn_smem = ATTN_SMEM_FLOATS * 4;
    cudaFuncSetAttribute(swa_kernel,
                         cudaFuncAttributeMaxDynamicSharedMemorySize, attn_smem);

    // 0) tf32 pre-rounding passes
    cvt_tf32_kernel<<<(T_TOK * DIMX / 4 + 255) / 256, 256>>>(x,    xc,    T_TOK * DIMX / 4);
    cvt_tf32_kernel<<<(QKVC * DIMX / 4 + 255) / 256, 256>>>(Wqkv, wqkvc, QKVC * DIMX / 4);
    cvt_tf32_kernel<<<(DIMX * DIMX / 4 + 255) / 256, 256>>>(Wo,   woc,   DIMX * DIMX / 4);

    // 1) qkv = x @ Wqkv^T + bqkv, RoPE fused into epilogue
    gemm_mma_tf32<true><<<dim3(QKVC / GBN, T_TOK / GBM), 256, GEMM_SMEM>>>(
        xc, wqkvc, bqkv, qkv, QKVC, DIMX, cosT, sinT);
    // 2) sliding-window attention with sink (emits tf32-rounded attn)
    swa_kernel<<<dim3(T_TOK / TQ, NKV), 256, attn_smem>>>(sinks);
    // 3) out = attn @ Wo^T + bo
    gemm_mma_tf32<false><<<dim3(DIMX / GBN, T_TOK / GBM), 256, GEMM_SMEM>>>(
        att, woc, bo, out, DIMX, DIMX, nullptr, nullptr);
}

// round 8
// speedup vs baseline: 1.2596x; 1.0791x over previous
#include <cuda_runtime.h>
#include <math.h>
#include <cstdint>
#include <cstddef>

// ---------------- problem constants ----------------
#define T_TOK   2048
#define DIMX    2048
#define QKVC    3072      // (32 + 2*8) * 64
#define NKV     8
#define WIN     128
#define TQ      16
#define KROWS   143

// Scratch (no allocs allowed)
__device__ float g_qkv[(size_t)T_TOK * QKVC];
__device__ float g_attn[(size_t)T_TOK * DIMX];
__device__ float g_xc[(size_t)T_TOK * DIMX];      // tf32-rounded x
__device__ float g_wqkvc[(size_t)QKVC * DIMX];    // tf32-rounded Wqkv
__device__ float g_woc[(size_t)DIMX * DIMX];      // tf32-rounded Wo

// ---------------- helpers ----------------
__device__ __forceinline__ uint32_t smem_u32(const void* p) {
    uint32_t a;
    asm("{ .reg .u64 t; cvta.to.shared.u64 t, %1; cvt.u32.u64 %0, t; }"
        : "=r"(a) : "l"(p));
    return a;
}
__device__ __forceinline__ float f2tf32f(float f) {
    uint32_t r;
    asm("cvt.rna.tf32.f32 %0, %1;" : "=r"(r) : "f"(f));
    return __uint_as_float(r);
}
__device__ __forceinline__ void mma_tf32(float* d, const uint32_t* a,
                                         const uint32_t* b) {
    asm volatile(
        "mma.sync.aligned.m16n8k8.row.col.f32.tf32.tf32.f32 "
        "{%0,%1,%2,%3}, {%4,%5,%6,%7}, {%8,%9}, {%0,%1,%2,%3};"
        : "+f"(d[0]), "+f"(d[1]), "+f"(d[2]), "+f"(d[3])
        : "r"(a[0]), "r"(a[1]), "r"(a[2]), "r"(a[3]), "r"(b[0]), "r"(b[1]));
}
__device__ __forceinline__ void ldsm_x4(uint32_t* r, uint32_t addr) {
    asm volatile(
        "ldmatrix.sync.aligned.m8n8.x4.shared.b16 {%0,%1,%2,%3}, [%4];"
        : "=r"(r[0]), "=r"(r[1]), "=r"(r[2]), "=r"(r[3]) : "r"(addr));
}

// ---------------- tf32 pre-round pass ----------------
__global__ void cvt_tf32_kernel(const float* __restrict__ in,
                                float* __restrict__ out, int n4)
{
    int i = blockIdx.x * blockDim.x + threadIdx.x;
    if (i < n4) {
        float4 v = *(const float4*)(in + (size_t)i * 4);
        v.x = f2tf32f(v.x); v.y = f2tf32f(v.y);
        v.z = f2tf32f(v.z); v.w = f2tf32f(v.w);
        *(float4*)(out + (size_t)i * 4) = v;
    }
}

// ---------------- tf32 mma.sync GEMM (ldmatrix frags, 2 CTAs/SM) ------------
// C[M, Ntot] = A[M, K] * B[Ntot, K]^T + bias.  Inputs MUST be tf32-pre-rounded.
// CTA tile 128x128x32, 3-stage cp.async pipeline, 256 threads.
#define GBM 128
#define GBN 128
#define GBK 32
#define PADW 36                    // 144B row stride; 144%128==16 -> LDSM conflict-free
#define SSTG (GBM * PADW * 2)      // floats per stage (A + B) = 9216
#define GEMM_SMEM (3 * SSTG * 4)   // 110592 bytes

template <bool DO_ROPE>
__global__ __launch_bounds__(256, 2)     // force <=128 regs -> 2 CTAs/SM
void gemm_mma_tf32(const float* __restrict__ A, const float* __restrict__ B,
                   const float* __restrict__ bias, float* __restrict__ C,
                   int Ntot, int K,
                   const float* __restrict__ cosT, const float* __restrict__ sinT)
{
    extern __shared__ float smf[];
    const uint32_t sbase = smem_u32(smf);

    const int tid  = threadIdx.x;
    const int lane = tid & 31;
    const int wid  = tid >> 5;
    const int warpM = wid & 3;       // 4 warps along M (32 rows each)
    const int warpN = wid >> 2;      // 2 warps along N (64 cols each)
    const int gid = lane >> 2;       // 0..7
    const int tig = lane & 3;        // 0..3

    const int m0 = blockIdx.y * GBM;
    const int n0 = blockIdx.x * GBN;
    const int niter = K / GBK;       // 64

    const float* Ag = A + (size_t)m0 * K;
    const float* Bg = B + (size_t)n0 * K;

    const int r0 = tid >> 3;         // 0..31
    const int c4 = (tid & 7) * 4;    // 0..28

    // ldmatrix per-lane address offsets (bytes, relative to stage base)
    const int q = lane >> 3;                         // 0..3 (tile id in x4)
    const int arow = ((q & 1) << 3) + (lane & 7);    // 0..15
    const int akof = (q >> 1) << 2;                  // 0 or 4
    const int brow = ((q >> 1) << 3) + (lane & 7);   // 0..15
    const int bkof = (q & 1) << 2;                   // 0 or 4
    const uint32_t a_off = (uint32_t)(((warpM * 32 + arow) * PADW + akof) * 4);
    const uint32_t b_off = (uint32_t)((GBM * PADW + (warpN * 64 + brow) * PADW + bkof) * 4);

    float acc[2][8][4];
#pragma unroll
    for (int mt = 0; mt < 2; mt++)
#pragma unroll
        for (int nt = 0; nt < 8; nt++)
#pragma unroll
            for (int z = 0; z < 4; z++) acc[mt][nt][z] = 0.f;

    auto issue = [&](int kt, int s) {
        if (kt < niter) {
            uint32_t abase = sbase + (uint32_t)(s * SSTG + r0 * PADW + c4) * 4;
            const float* ap = Ag + (size_t)r0 * K + kt * GBK + c4;
            const float* bp = Bg + (size_t)r0 * K + kt * GBK + c4;
            uint32_t bbase = abase + GBM * PADW * 4;
#pragma unroll
            for (int i = 0; i < 4; i++) {
                asm volatile("cp.async.cg.shared.global [%0], [%1], 16;"
                             :: "r"(abase + i * 32 * PADW * 4),
                                "l"(ap + (size_t)i * 32 * K) : "memory");
                asm volatile("cp.async.cg.shared.global [%0], [%1], 16;"
                             :: "r"(bbase + i * 32 * PADW * 4),
                                "l"(bp + (size_t)i * 32 * K) : "memory");
            }
        }
        asm volatile("cp.async.commit_group;" ::: "memory");
    };

    issue(0, 0);
    issue(1, 1);

    for (int it = 0; it < niter; it++) {
        asm volatile("cp.async.wait_group 1;" ::: "memory");
        __syncthreads();                 // single barrier per iter

        // prefetch next stage immediately (stage (it+2)%3 == (it-1)%3: safe,
        // the barrier above proves everyone finished reading it)
        issue(it + 2, (it + 2) % 3);

        const uint32_t stg = sbase + (uint32_t)((it % 3) * SSTG) * 4;
        const uint32_t aB = stg + a_off;
        const uint32_t bB = stg + b_off;

#pragma unroll
        for (int ks = 0; ks < 4; ks++) {
            const uint32_t kb = ks * 32;           // 8 floats = 32 bytes
            uint32_t afr[2][4];
            ldsm_x4(afr[0], aB + kb);
            ldsm_x4(afr[1], aB + kb + 16 * PADW * 4);
            uint32_t bfr[4][4];                     // [pair][b0,b1,b0',b1']
            ldsm_x4(bfr[0], bB + kb);
            ldsm_x4(bfr[1], bB + kb + 16 * PADW * 4);
            ldsm_x4(bfr[2], bB + kb + 32 * PADW * 4);
            ldsm_x4(bfr[3], bB + kb + 48 * PADW * 4);
#pragma unroll
            for (int mt = 0; mt < 2; mt++)
#pragma unroll
                for (int p = 0; p < 4; p++) {
                    mma_tf32(acc[mt][2 * p + 0], afr[mt], &bfr[p][0]);
                    mma_tf32(acc[mt][2 * p + 1], afr[mt], &bfr[p][2]);
                }
        }
    }

    // ---- epilogue: bias + optional fused RoPE (cols < 2560 are q/k heads) --
    const bool rope_tile = DO_ROPE && (n0 < 2560);
#pragma unroll
    for (int mt = 0; mt < 2; mt++) {
        int row = m0 + warpM * 32 + mt * 16 + gid;   // token for z0,z1; row+8 for z2,z3
#pragma unroll
        for (int np = 0; np < 4; np++) {
            int colL = n0 + warpN * 64 + np * 8 + 2 * tig;   // colL % 64 in [0,31)
            int colH = colL + 32;
            float L[4], H[4];
#pragma unroll
            for (int z = 0; z < 4; z++) {
                L[z] = acc[mt][np][z]     + __ldg(&bias[colL + (z & 1)]);
                H[z] = acc[mt][np + 4][z] + __ldg(&bias[colH + (z & 1)]);
            }
            if (rope_tile) {
                int dl = colL & 63;                       // 0..30
                const float* c1 = cosT + (size_t)row * 64;
                const float* s1 = sinT + (size_t)row * 64;
                const float* c2 = c1 + 8 * 64;
                const float* s2 = s1 + 8 * 64;
#pragma unroll
                for (int z = 0; z < 4; z++) {
                    const float* cc = (z < 2) ? c1 : c2;
                    const float* ss = (z < 2) ? s1 : s2;
                    int d = dl + (z & 1);
                    float lo = L[z], hi = H[z];
                    L[z] = lo * cc[d]      - hi * ss[d];
                    H[z] = hi * cc[d + 32] + lo * ss[d + 32];
                }
            }
            *(float2*)(C + (size_t)row * Ntot + colL)       = make_float2(L[0], L[1]);
            *(float2*)(C + (size_t)(row + 8) * Ntot + colL) = make_float2(L[2], L[3]);
            *(float2*)(C + (size_t)row * Ntot + colH)       = make_float2(H[0], H[1]);
            *(float2*)(C + (size_t)(row + 8) * Ntot + colH) = make_float2(H[2], H[3]);
        }
    }
}

// ---------------- SWA (emits tf32-rounded attn for GEMM2) ----------------
#define ATTN_SMEM_FLOATS (64*144 + 144*64 + 64*64 + 64*129 + 64)

__global__ __launch_bounds__(256, 1)
void swa_kernel(const float* __restrict__ sinks)
{
    extern __shared__ float sm[];
    float* Kt  = sm;
    float* V   = Kt + 64 * 144;
    float* Qt  = V  + 144 * 64;
    float* S   = Qt + 64 * 64;
    float* den = S  + 64 * 129;

    const int tid = threadIdx.x;
    const int t0  = blockIdx.x * TQ;
    const int kvh = blockIdx.y;

    for (int idx = tid; idx < KROWS * 64; idx += 256) {
        int u = idx >> 6, d = idx & 63;
        int j = t0 - 127 + u;
        float kv = 0.f, vv = 0.f;
        if (j >= 0) {
            const float* r = g_qkv + (size_t)j * QKVC;
            kv = r[2048 + kvh * 64 + d];
            vv = r[2560 + kvh * 64 + d];
        }
        Kt[d * 144 + u] = kv;
        V[u * 64 + d]   = vv;
    }
    for (int idx = tid; idx < 64 * 64; idx += 256) {
        int r = idx >> 6, d = idx & 63;
        int i = r >> 2, g = r & 3;
        Qt[d * 64 + r] =
            g_qkv[(size_t)(t0 + i) * QKVC + (kvh * 4 + g) * 64 + d] * 0.125f;
    }
    __syncthreads();

    {
        const int c = tid & 31;
#pragma unroll
        for (int half = 0; half < 2; half++) {
            const int a = (tid >> 5) + half * 8;
            float acc[16];
#pragma unroll
            for (int z = 0; z < 16; z++) acc[z] = 0.f;
#pragma unroll 8
            for (int d = 0; d < 64; d++) {
                float q0 = Qt[d * 64 + 4 * a + 0];
                float q1 = Qt[d * 64 + 4 * a + 1];
                float q2 = Qt[d * 64 + 4 * a + 2];
                float q3 = Qt[d * 64 + 4 * a + 3];
                float k0 = Kt[d * 144 + a + c];
                float k1 = Kt[d * 144 + a + c + 32];
                float k2 = Kt[d * 144 + a + c + 64];
                float k3 = Kt[d * 144 + a + c + 96];
                acc[0]  += q0 * k0; acc[1]  += q0 * k1; acc[2]  += q0 * k2; acc[3]  += q0 * k3;
                acc[4]  += q1 * k0; acc[5]  += q1 * k1; acc[6]  += q1 * k2; acc[7]  += q1 * k3;
                acc[8]  += q2 * k0; acc[9]  += q2 * k1; acc[10] += q2 * k2; acc[11] += q2 * k3;
                acc[12] += q3 * k0; acc[13] += q3 * k1; acc[14] += q3 * k2; acc[15] += q3 * k3;
            }
#pragma unroll
            for (int g = 0; g < 4; g++)
#pragma unroll
                for (int kk = 0; kk < 4; kk++)
                    S[(4 * a + g) * 129 + c + kk * 32] = acc[g * 4 + kk];
        }
    }
    __syncthreads();

    {
        const int warp = tid >> 5, lane = tid & 31;
        for (int rr = 0; rr < 8; rr++) {
            int r = warp * 8 + rr;
            int i = r >> 2, g = r & 3;
            int t = t0 + i;
            int wmin = 127 - t;
            float s[4];
#pragma unroll
            for (int kk = 0; kk < 4; kk++) {
                int w = lane + kk * 32;
                float v = S[r * 129 + w];
                s[kk] = (w < wmin) ? -1e30f : v;
            }
            float m = fmaxf(fmaxf(s[0], s[1]), fmaxf(s[2], s[3]));
#pragma unroll
            for (int o = 16; o; o >>= 1)
                m = fmaxf(m, __shfl_xor_sync(0xffffffffu, m, o));
            float snk = __ldg(&sinks[kvh * 4 + g]);
            m = fmaxf(m, snk);
            float sum = 0.f;
#pragma unroll
            for (int kk = 0; kk < 4; kk++) {
                float e = __expf(s[kk] - m);
                S[r * 129 + lane + kk * 32] = e;
                sum += e;
            }
#pragma unroll
            for (int o = 16; o; o >>= 1)
                sum += __shfl_xor_sync(0xffffffffu, sum, o);
            sum += __expf(snk - m);
            if (lane == 0) den[r] = 1.0f / sum;
        }
    }
    __syncthreads();

    {
        const int b = tid >> 4;
        const int e = tid & 15;
        float o_[4][4];
#pragma unroll
        for (int g = 0; g < 4; g++)
#pragma unroll
            for (int z = 0; z < 4; z++) o_[g][z] = 0.f;

        for (int w = 0; w < 128; w++) {
            float4 v4 = *(const float4*)(V + (b + w) * 64 + e * 4);
#pragma unroll
            for (int g = 0; g < 4; g++) {
                float p = S[(4 * b + g) * 129 + w];
                o_[g][0] += p * v4.x;
                o_[g][1] += p * v4.y;
                o_[g][2] += p * v4.z;
                o_[g][3] += p * v4.w;
            }
        }
        const int t = t0 + b;
#pragma unroll
        for (int g = 0; g < 4; g++) {
            float inv = den[4 * b + g];
            float4 r;
            r.x = f2tf32f(o_[g][0] * inv);
            r.y = f2tf32f(o_[g][1] * inv);
            r.z = f2tf32f(o_[g][2] * inv);
            r.w = f2tf32f(o_[g][3] * inv);
            *(float4*)(g_attn + (size_t)t * DIMX + (kvh * 4 + g) * 64 + e * 4) = r;
        }
    }
}

// ---------------- host ----------------
extern "C" void kernel_launch(void* const* d_in, const int* in_sizes, int n_in,
                              void* d_out, int out_size)
{
    (void)in_sizes; (void)n_in; (void)out_size;
    const float* x     = (const float*)d_in[0];
    const float* cosT  = (const float*)d_in[1];
    const float* sinT  = (const float*)d_in[2];
    const float* Wqkv  = (const float*)d_in[3];
    const float* bqkv  = (const float*)d_in[4];
    const float* Wo    = (const float*)d_in[5];
    const float* bo    = (const float*)d_in[6];
    const float* sinks = (const float*)d_in[7];
    float* out = (float*)d_out;

    float *qkv = nullptr, *att = nullptr;
    float *xc = nullptr, *wqkvc = nullptr, *woc = nullptr;
    cudaGetSymbolAddress((void**)&qkv,   g_qkv);
    cudaGetSymbolAddress((void**)&att,   g_attn);
    cudaGetSymbolAddress((void**)&xc,    g_xc);
    cudaGetSymbolAddress((void**)&wqkvc, g_wqkvc);
    cudaGetSymbolAddress((void**)&woc,   g_woc);

    cudaFuncSetAttribute(gemm_mma_tf32<true>,
                         cudaFuncAttributeMaxDynamicSharedMemorySize, GEMM_SMEM);
    cudaFuncSetAttribute(gemm_mma_tf32<false>,
                         cudaFuncAttributeMaxDynamicSharedMemorySize, GEMM_SMEM);
    const int attn_smem = ATTN_SMEM_FLOATS * 4;
    cudaFuncSetAttribute(swa_kernel,
                         cudaFuncAttributeMaxDynamicSharedMemorySize, attn_smem);

    // 0) tf32 pre-rounding passes
    cvt_tf32_kernel<<<(T_TOK * DIMX / 4 + 255) / 256, 256>>>(x,    xc,    T_TOK * DIMX / 4);
    cvt_tf32_kernel<<<(QKVC * DIMX / 4 + 255) / 256, 256>>>(Wqkv, wqkvc, QKVC * DIMX / 4);
    cvt_tf32_kernel<<<(DIMX * DIMX / 4 + 255) / 256, 256>>>(Wo,   woc,   DIMX * DIMX / 4);

    // 1) qkv = x @ Wqkv^T + bqkv, RoPE fused into epilogue
    gemm_mma_tf32<true><<<dim3(QKVC / GBN, T_TOK / GBM), 256, GEMM_SMEM>>>(
        xc, wqkvc, bqkv, qkv, QKVC, DIMX, cosT, sinT);
    // 2) sliding-window attention with sink (emits tf32-rounded attn)
    swa_kernel<<<dim3(T_TOK / TQ, NKV), 256, attn_smem>>>(sinks);
    // 3) out = attn @ Wo^T + bo
    gemm_mma_tf32<false><<<dim3(DIMX / GBN, T_TOK / GBM), 256, GEMM_SMEM>>>(
        att, woc, bo, out, DIMX, DIMX, nullptr, nullptr);
}